// round 14
// baseline (speedup 1.0000x reference)
#include <cuda_runtime.h>
#include <cuda_bf16.h>
#include <cstdint>

// AttentionBlock fused kernel, sm_103a. Round 13:
// Mixed precision by error sensitivity: fp8 (e4m3, m16n8k32) for G = X@M8 and
// S = G@X^T (errors killed by the 1/2896 softmax scale); bf16 for T = P@X and
// out = T@W9 (errors visible in output). Fragment-order weights from L2.
// 2 CTAs/SM, 5 block barriers.

#define CH    256
#define LDH   264   // bf16 tile row stride (halves)
#define LDP   72    // bf16 P tile stride
#define LDSS  68    // fp32 score stride
#define LD8   272   // fp8 tile row stride (bytes)

// M8 = Wq@Wk^T in fp8 m16n8k32 fragment order:
//   uint2 per lane per (n8, k32) tile; idx = (n8*8 + k32)*32 + lane.
__device__ uint2 g_M8f[32 * 8 * 32];
// W9 = Wv@Wo in bf16 m16n8k16 fragment order (R11 layout):
//   uint2 per lane per (n8, k16) tile; idx = (n8*16 + k16)*32 + lane.
__device__ uint2 g_W9f[32 * 16 * 32];
__device__ float g_b9[CH];             // bv @ Wo + bo
__device__ float g_w8[CH];             // Wk @ bq
__device__ float g_s8;                 // bk . bq

__device__ __forceinline__ uint16_t e4m3x2(float hi, float lo) {
    uint16_t h;
    asm("cvt.rn.satfinite.e4m3x2.f32 %0, %1, %2;" : "=h"(h) : "f"(hi), "f"(lo));
    return h;   // byte0 = lo, byte1 = hi
}

// Dynamic smem for setup: As [32][256] fp32 + Bs [256][33] fp32
#define SETUP_SMEM_FLOATS (8192 + 8448)
#define SETUP_SMEM_BYTES  (SETUP_SMEM_FLOATS * 4)

__global__ void setup_kernel(const float* __restrict__ Wq, const float* __restrict__ Wk,
                             const float* __restrict__ Wv, const float* __restrict__ Wo,
                             const float* __restrict__ bq, const float* __restrict__ bk,
                             const float* __restrict__ bv, const float* __restrict__ bo) {
    extern __shared__ float sdyn[];
    const int tid = threadIdx.x;
    const int z = blockIdx.z;

    if (z == 2) {
        const int id = blockIdx.y * 8 + blockIdx.x;
        if (id < 8) {
            int r = id * 32 + (tid >> 3);
            int q = tid & 7;
            const float4* wk = (const float4*)(Wk + r * CH + q * 32);
            float s = 0.f;
            #pragma unroll
            for (int j = 0; j < 8; j++) {
                float4 v = wk[j];
                int d = q * 32 + j * 4;
                s += v.x * bq[d] + v.y * bq[d + 1] + v.z * bq[d + 2] + v.w * bq[d + 3];
            }
            s += __shfl_xor_sync(0xffffffffu, s, 1);
            s += __shfl_xor_sync(0xffffffffu, s, 2);
            s += __shfl_xor_sync(0xffffffffu, s, 4);
            if (q == 0) g_w8[r] = s;
        } else if (id == 8) {
            float p = bk[tid] * bq[tid];
            #pragma unroll
            for (int d = 16; d > 0; d >>= 1) p += __shfl_xor_sync(0xffffffffu, p, d);
            if ((tid & 31) == 0) sdyn[tid >> 5] = p;
            __syncthreads();
            if (tid == 0) {
                float s = 0.f;
                #pragma unroll
                for (int w = 0; w < 8; w++) s += sdyn[w];
                g_s8 = s;
            }
        } else if (id >= 16 && id < 24) {
            int c0 = (id - 16) * 32;
            int tx = tid & 31, ty = tid >> 5;
            int c = c0 + tx;
            float s = 0.f;
            #pragma unroll 8
            for (int i = 0; i < 32; i++) {
                int d = ty + 8 * i;
                s += bv[d] * Wo[d * CH + c];
            }
            sdyn[ty * 33 + tx] = s;
            __syncthreads();
            if (ty == 0) {
                float t = 0.f;
                #pragma unroll
                for (int w = 0; w < 8; w++) t += sdyn[w * 33 + tx];
                g_b9[c] = t + bo[c];
            }
        }
        return;
    }

    float* As = sdyn;              // [32][256]
    float* Bs = sdyn + 8192;       // [256][33]
    const int tx = tid & 31, ty = tid >> 5;
    const int a0 = blockIdx.y * 32, b0 = blockIdx.x * 32;
    const float* A = z ? Wv : Wq;

    #pragma unroll
    for (int k = 0; k < 8; k++) {
        int idx = tid + k * 256;
        int i = idx >> 6, j = (idx & 63) * 4;
        float4 v = *(const float4*)(A + (a0 + i) * CH + j);
        As[i * 256 + j] = v.x; As[i * 256 + j + 1] = v.y;
        As[i * 256 + j + 2] = v.z; As[i * 256 + j + 3] = v.w;
    }
    if (z == 0) {
        #pragma unroll
        for (int k = 0; k < 8; k++) {
            int idx = tid + k * 256;
            int i = idx >> 6, j = (idx & 63) * 4;
            float4 v = *(const float4*)(Wk + (b0 + i) * CH + j);
            Bs[j * 33 + i] = v.x; Bs[(j + 1) * 33 + i] = v.y;
            Bs[(j + 2) * 33 + i] = v.z; Bs[(j + 3) * 33 + i] = v.w;
        }
    } else {
        #pragma unroll
        for (int k = 0; k < 8; k++) {
            int idx = tid + k * 256;
            int j = idx >> 3, i4 = (idx & 7) * 4;
            float4 v = *(const float4*)(Wo + j * CH + b0 + i4);
            Bs[j * 33 + i4] = v.x; Bs[j * 33 + i4 + 1] = v.y;
            Bs[j * 33 + i4 + 2] = v.z; Bs[j * 33 + i4 + 3] = v.w;
        }
    }
    __syncthreads();

    float acc[4] = {0.f, 0.f, 0.f, 0.f};
    #pragma unroll 4
    for (int dd = 0; dd < 256; dd++) {
        float b = Bs[dd * 33 + tx];
        #pragma unroll
        for (int r = 0; r < 4; r++) acc[r] += As[(ty + 8 * r) * 256 + dd] * b;
    }

    if (z == 0) {   // fp8 fragment scatter (m16n8k32)
        uint8_t* dst = (uint8_t*)g_M8f;
        #pragma unroll
        for (int r = 0; r < 4; r++) {
            int a = a0 + ty + 8 * r;      // k-dim
            int b = b0 + tx;              // n-dim
            int idx = ((((b >> 3) * 8 + (a >> 5)) * 32) + (b & 7) * 4 + ((a >> 2) & 3)) * 8
                    + ((a >> 4) & 1) * 4 + (a & 3);
            dst[idx] = (uint8_t)e4m3x2(0.f, acc[r]);
        }
    } else {        // bf16 fragment scatter (m16n8k16)
        __nv_bfloat16* dst = (__nv_bfloat16*)g_W9f;
        #pragma unroll
        for (int r = 0; r < 4; r++) {
            int a = a0 + ty + 8 * r;      // k-dim
            int b = b0 + tx;              // n-dim
            int idx = ((((b >> 3) * 16 + (a >> 4)) * 32) + (b & 7) * 4 + ((a & 7) >> 1)) * 4
                    + ((a >> 3) & 1) * 2 + (a & 1);
            dst[idx] = __float2bfloat16(acc[r]);
        }
    }
}

// ---- mma helpers ----
__device__ __forceinline__ uint32_t smem_u32(const void* p) {
    return (uint32_t)__cvta_generic_to_shared(p);
}
__device__ __forceinline__ void ldm_x4(uint32_t addr, uint32_t& a0, uint32_t& a1,
                                       uint32_t& a2, uint32_t& a3) {
    asm volatile("ldmatrix.sync.aligned.m8n8.x4.shared.b16 {%0,%1,%2,%3}, [%4];"
                 : "=r"(a0), "=r"(a1), "=r"(a2), "=r"(a3) : "r"(addr));
}
__device__ __forceinline__ void ldm_x4t(uint32_t addr, uint32_t& b0, uint32_t& b1,
                                        uint32_t& b2, uint32_t& b3) {
    asm volatile("ldmatrix.sync.aligned.m8n8.x4.trans.shared.b16 {%0,%1,%2,%3}, [%4];"
                 : "=r"(b0), "=r"(b1), "=r"(b2), "=r"(b3) : "r"(addr));
}
__device__ __forceinline__ void mma_bf16(float c[4],
                                         uint32_t a0, uint32_t a1, uint32_t a2, uint32_t a3,
                                         uint32_t b0, uint32_t b1) {
    asm volatile("mma.sync.aligned.m16n8k16.row.col.f32.bf16.bf16.f32 "
                 "{%0,%1,%2,%3}, {%4,%5,%6,%7}, {%8,%9}, {%0,%1,%2,%3};"
                 : "+f"(c[0]), "+f"(c[1]), "+f"(c[2]), "+f"(c[3])
                 : "r"(a0), "r"(a1), "r"(a2), "r"(a3), "r"(b0), "r"(b1));
}
__device__ __forceinline__ void mma_fp8(float c[4],
                                        uint32_t a0, uint32_t a1, uint32_t a2, uint32_t a3,
                                        uint32_t b0, uint32_t b1) {
    asm volatile("mma.sync.aligned.m16n8k32.row.col.f32.e4m3.e4m3.f32 "
                 "{%0,%1,%2,%3}, {%4,%5,%6,%7}, {%8,%9}, {%0,%1,%2,%3};"
                 : "+f"(c[0]), "+f"(c[1]), "+f"(c[2]), "+f"(c[3])
                 : "r"(a0), "r"(a1), "r"(a2), "r"(a3), "r"(b0), "r"(b1));
}

// FP8 GEMM (G phase), B fragments from L2 with next-step prefetch.
__device__ __forceinline__ void gemm_f8(const uint2* __restrict__ Wf,
                                        const uint8_t* sA8,
                                        float acc[2][8][4],
                                        int lane, int r0, int nb) {
    #pragma unroll
    for (int mt = 0; mt < 2; mt++)
        #pragma unroll
        for (int nt = 0; nt < 8; nt++)
            acc[mt][nt][0] = acc[mt][nt][1] = acc[mt][nt][2] = acc[mt][nt][3] = 0.f;

    const int grp = lane >> 2, tig = lane & 3;
    const uint2* wb = Wf + ((nb >> 3) * 8) * 32 + lane;
    const uint8_t* aB = sA8 + tig * 4;

    uint2 vc[8], vn[8];
    #pragma unroll
    for (int nt = 0; nt < 8; nt++) vc[nt] = wb[(nt * 8) * 32];

    #pragma unroll
    for (int kc = 0; kc < 8; kc++) {
        if (kc < 7) {
            #pragma unroll
            for (int nt = 0; nt < 8; nt++) vn[nt] = wb[(nt * 8 + kc + 1) * 32];
        }
        uint32_t a[2][4];
        #pragma unroll
        for (int mt = 0; mt < 2; mt++) {
            const uint8_t* ar = aB + (r0 + mt * 16 + grp) * LD8 + kc * 32;
            a[mt][0] = *(const uint32_t*)(ar);
            a[mt][1] = *(const uint32_t*)(ar + 8 * LD8);
            a[mt][2] = *(const uint32_t*)(ar + 16);
            a[mt][3] = *(const uint32_t*)(ar + 8 * LD8 + 16);
        }
        #pragma unroll
        for (int nt = 0; nt < 8; nt++) {
            mma_fp8(acc[0][nt], a[0][0], a[0][1], a[0][2], a[0][3], vc[nt].x, vc[nt].y);
            mma_fp8(acc[1][nt], a[1][0], a[1][1], a[1][2], a[1][3], vc[nt].x, vc[nt].y);
        }
        if (kc < 7) {
            #pragma unroll
            for (int nt = 0; nt < 8; nt++) vc[nt] = vn[nt];
        }
    }
}

// BF16 GEMM (out phase), B fragments from L2 with next-step prefetch.
__device__ __forceinline__ void gemm_f(const uint2* __restrict__ Wf,
                                       const __nv_bfloat16* sA,
                                       float acc[2][8][4],
                                       int lane, int r0, int nb) {
    #pragma unroll
    for (int mt = 0; mt < 2; mt++)
        #pragma unroll
        for (int nt = 0; nt < 8; nt++)
            acc[mt][nt][0] = acc[mt][nt][1] = acc[mt][nt][2] = acc[mt][nt][3] = 0.f;

    const uint2* wb = Wf + ((nb >> 3) * 16) * 32 + lane;
    uint2 vc[8], vn[8];
    #pragma unroll
    for (int nt = 0; nt < 8; nt++) vc[nt] = wb[(nt * 16) * 32];

    #pragma unroll
    for (int ks = 0; ks < 16; ks++) {
        if (ks < 15) {
            #pragma unroll
            for (int nt = 0; nt < 8; nt++) vn[nt] = wb[(nt * 16 + ks + 1) * 32];
        }
        uint32_t a[2][4];
        #pragma unroll
        for (int mt = 0; mt < 2; mt++)
            ldm_x4(smem_u32(sA + (r0 + mt * 16 + (lane & 15)) * LDH
                            + ks * 16 + ((lane >> 4) << 3)),
                   a[mt][0], a[mt][1], a[mt][2], a[mt][3]);
        #pragma unroll
        for (int nt = 0; nt < 8; nt++) {
            mma_bf16(acc[0][nt], a[0][0], a[0][1], a[0][2], a[0][3], vc[nt].x, vc[nt].y);
            mma_bf16(acc[1][nt], a[1][0], a[1][1], a[1][2], a[1][3], vc[nt].x, vc[nt].y);
        }
        if (ks < 15) {
            #pragma unroll
            for (int nt = 0; nt < 8; nt++) vc[nt] = vn[nt];
        }
    }
}

// SMEM layout (bytes):
// sX   bf16 [64][264] @ 0       (33792)
// sX8  fp8  [64][272] @ 33792   (17408)
// sG8  fp8  [64][272] @ 51200   (17408)
// sT   bf16 [64][264] @ 68608   (33792)  -- sS fp32 [64][68] overlays (17408)
// sP   bf16 [64][72]  @ 102400  (9216)
// sC   f32  [64]      @ 111616
// sBias f32 [256]     @ 111872
#define SMEM_BYTES 112896

__global__ void __launch_bounds__(256, 2)
attn_kernel(const float* __restrict__ x, float* __restrict__ out)
{
    extern __shared__ char smem_raw[];
    __nv_bfloat16* sX  = (__nv_bfloat16*)smem_raw;
    uint8_t*       sX8 = (uint8_t*)(smem_raw + 33792);
    uint8_t*       sG8 = (uint8_t*)(smem_raw + 51200);
    __nv_bfloat16* sT  = (__nv_bfloat16*)(smem_raw + 68608);
    float*         sS  = (float*)sT;
    __nv_bfloat16* sP  = (__nv_bfloat16*)(smem_raw + 102400);
    float*         sC  = (float*)(smem_raw + 111616);
    float*      sBias  = (float*)(smem_raw + 111872);

    const int tid  = threadIdx.x;
    const int wid  = tid >> 5;
    const int lane = tid & 31;
    const int grp  = lane >> 2;
    const int tig  = lane & 3;

    const size_t base = (size_t)blockIdx.x * 64 * CH;
    const float* xrow = x   + base;
    float*       orow = out + base;

    // ---------------- Phase 0: bias + x tile (fp32 -> bf16 + fp8) ----------------
    sBias[tid] = g_b9[tid];
    {
        const float4* xv = (const float4*)xrow;
        #pragma unroll
        for (int t = 0; t < 16; t++) {
            int i = tid + t * 256;
            int row = i >> 6;
            int colf = (i & 63) * 4;
            float4 v = xv[i];
            __nv_bfloat162* d = (__nv_bfloat162*)(sX + row * LDH + colf);
            d[0] = __floats2bfloat162_rn(v.x, v.y);
            d[1] = __floats2bfloat162_rn(v.z, v.w);
            uint32_t p8 = (uint32_t)e4m3x2(v.y, v.x)
                        | ((uint32_t)e4m3x2(v.w, v.z) << 16);
            *(uint32_t*)(sX8 + row * LD8 + colf) = p8;
        }
    }
    __syncthreads();

    // c_j = x_j . w8 + s8 from sX (bf16; 4 threads per row)
    {
        int row = tid >> 2, q = tid & 3;
        const __nv_bfloat162* xr = (const __nv_bfloat162*)(sX + row * LDH + q * 64);
        float s = 0.f;
        #pragma unroll
        for (int j = 0; j < 32; j++) {
            float2 v = __bfloat1622float2(xr[j]);
            int c = q * 64 + j * 2;
            s += v.x * g_w8[c] + v.y * g_w8[c + 1];
        }
        s += __shfl_xor_sync(0xffffffffu, s, 1);
        s += __shfl_xor_sync(0xffffffffu, s, 2);
        if (q == 0) sC[row] = s + g_s8;
    }
    // sC consumed after the post-G barrier

    const int r0 = (wid >> 2) * 32;   // warp's 32 rows
    const int nb = (wid & 3) * 64;    // warp's 64 cols

    float acc[2][8][4];

    // ---------------- G = X8 @ M8 -> sG8 (fp8) ----------------
    gemm_f8(g_M8f, sX8, acc, lane, r0, nb);
    #pragma unroll
    for (int mt = 0; mt < 2; mt++)
        #pragma unroll
        for (int nt = 0; nt < 8; nt++) {
            int col = nb + nt * 8 + tig * 2;
            int ra = r0 + mt * 16 + grp;
            *(uint16_t*)(sG8 + ra * LD8 + col) = e4m3x2(acc[mt][nt][1], acc[mt][nt][0]);
            *(uint16_t*)(sG8 + (ra + 8) * LD8 + col) = e4m3x2(acc[mt][nt][3], acc[mt][nt][2]);
        }
    __syncthreads();

    // ------- S = (G8 X8^T + c_j)*scale -> sS (fp32), ALL 8 warps, fp8 mma -------
    {
        const int r0s = (wid & 3) * 16;   // 16 rows
        const int j0  = (wid >> 2) * 32;  // 32 cols
        float sa[4][4];
        #pragma unroll
        for (int nt = 0; nt < 4; nt++)
            sa[nt][0] = sa[nt][1] = sa[nt][2] = sa[nt][3] = 0.f;
        #pragma unroll
        for (int kc = 0; kc < 8; kc++) {
            const uint8_t* ar = sG8 + (r0s + grp) * LD8 + kc * 32 + tig * 4;
            uint32_t a0 = *(const uint32_t*)(ar);
            uint32_t a1 = *(const uint32_t*)(ar + 8 * LD8);
            uint32_t a2 = *(const uint32_t*)(ar + 16);
            uint32_t a3 = *(const uint32_t*)(ar + 8 * LD8 + 16);
            #pragma unroll
            for (int nt = 0; nt < 4; nt++) {
                const uint8_t* br = sX8 + (j0 + nt * 8 + grp) * LD8 + kc * 32 + tig * 4;
                uint32_t b0 = *(const uint32_t*)(br);
                uint32_t b1 = *(const uint32_t*)(br + 16);
                mma_fp8(sa[nt], a0, a1, a2, a3, b0, b1);
            }
        }
        const float SCALE = 1.0f / (256.0f * 16.0f * 0.70710678118654752f);
        #pragma unroll
        for (int nt = 0; nt < 4; nt++) {
            int col = j0 + nt * 8 + tig * 2;
            float c0 = sC[col], c1 = sC[col + 1];
            sS[(r0s + grp) * LDSS + col]         = (sa[nt][0] + c0) * SCALE;
            sS[(r0s + grp) * LDSS + col + 1]     = (sa[nt][1] + c1) * SCALE;
            sS[(r0s + grp + 8) * LDSS + col]     = (sa[nt][2] + c0) * SCALE;
            sS[(r0s + grp + 8) * LDSS + col + 1] = (sa[nt][3] + c1) * SCALE;
        }
    }
    __syncthreads();

    // ---------------- softmax rows -> P (bf16); 4 threads/row ----------------
    {
        int row = tid >> 2, t4 = tid & 3;
        const float* sr = sS + row * LDSS + t4 * 16;
        float v[16];
        #pragma unroll
        for (int i = 0; i < 16; i++) v[i] = sr[i];
        float m = v[0];
        #pragma unroll
        for (int i = 1; i < 16; i++) m = fmaxf(m, v[i]);
        m = fmaxf(m, __shfl_xor_sync(0xffffffffu, m, 1));
        m = fmaxf(m, __shfl_xor_sync(0xffffffffu, m, 2));
        float s = 0.f;
        #pragma unroll
        for (int i = 0; i < 16; i++) { v[i] = __expf(v[i] - m); s += v[i]; }
        s += __shfl_xor_sync(0xffffffffu, s, 1);
        s += __shfl_xor_sync(0xffffffffu, s, 2);
        float inv = 1.0f / s;
        __nv_bfloat162* dp = (__nv_bfloat162*)(sP + row * LDP + t4 * 16);
        #pragma unroll
        for (int i = 0; i < 8; i++)
            dp[i] = __floats2bfloat162_rn(v[2 * i] * inv, v[2 * i + 1] * inv);
    }
    __syncthreads();

    // ---------------- T = P @ X (bf16) -> sT (scores dead) ----------------
    {
        #pragma unroll
        for (int mt = 0; mt < 2; mt++)
            #pragma unroll
            for (int nt = 0; nt < 8; nt++)
                acc[mt][nt][0] = acc[mt][nt][1] = acc[mt][nt][2] = acc[mt][nt][3] = 0.f;
        #pragma unroll
        for (int ks = 0; ks < 4; ks++) {
            uint32_t a[2][4];
            #pragma unroll
            for (int mt = 0; mt < 2; mt++)
                ldm_x4(smem_u32(sP + (r0 + mt * 16 + (lane & 15)) * LDP
                                + ks * 16 + ((lane >> 4) << 3)),
                       a[mt][0], a[mt][1], a[mt][2], a[mt][3]);
            #pragma unroll
            for (int nt16 = 0; nt16 < 4; nt16++) {
                uint32_t b0, b1, b2, b3;
                ldm_x4t(smem_u32(sX + (ks * 16 + (lane & 15)) * LDH
                                 + nb + nt16 * 16 + ((lane >> 4) << 3)),
                        b0, b1, b2, b3);
                #pragma unroll
                for (int mt = 0; mt < 2; mt++) {
                    mma_bf16(acc[mt][2 * nt16],     a[mt][0], a[mt][1], a[mt][2], a[mt][3], b0, b1);
                    mma_bf16(acc[mt][2 * nt16 + 1], a[mt][0], a[mt][1], a[mt][2], a[mt][3], b2, b3);
                }
            }
        }
        #pragma unroll
        for (int mt = 0; mt < 2; mt++)
            #pragma unroll
            for (int nt = 0; nt < 8; nt++) {
                int col = nb + nt * 8 + tig * 2;
                int ra = r0 + mt * 16 + grp;
                *(__nv_bfloat162*)(sT + ra * LDH + col) =
                    __floats2bfloat162_rn(acc[mt][nt][0], acc[mt][nt][1]);
                *(__nv_bfloat162*)(sT + (ra + 8) * LDH + col) =
                    __floats2bfloat162_rn(acc[mt][nt][2], acc[mt][nt][3]);
            }
    }
    __syncthreads();

    // ---------------- out = T @ W9 + b9 + x (bf16) ----------------
    gemm_f(g_W9f, sT, acc, lane, r0, nb);
    #pragma unroll
    for (int mt = 0; mt < 2; mt++)
        #pragma unroll
        for (int nt = 0; nt < 8; nt++) {
            int col = nb + nt * 8 + tig * 2;
            float b0v = sBias[col], b1v = sBias[col + 1];
            int ra = r0 + mt * 16 + grp, rb = ra + 8;
            float2 xa = *(const float2*)(xrow + ra * CH + col);
            float2 xb = *(const float2*)(xrow + rb * CH + col);
            *(float2*)(orow + ra * CH + col) =
                make_float2(acc[mt][nt][0] + b0v + xa.x, acc[mt][nt][1] + b1v + xa.y);
            *(float2*)(orow + rb * CH + col) =
                make_float2(acc[mt][nt][2] + b0v + xb.x, acc[mt][nt][3] + b1v + xb.y);
        }
}

extern "C" void kernel_launch(void* const* d_in, const int* in_sizes, int n_in,
                              void* d_out, int out_size) {
    const float* x  = (const float*)d_in[0];
    const float* Wq = (const float*)d_in[1];
    const float* bq = (const float*)d_in[2];
    const float* Wk = (const float*)d_in[3];
    const float* bk = (const float*)d_in[4];
    const float* Wv = (const float*)d_in[5];
    const float* bv = (const float*)d_in[6];
    const float* Wo = (const float*)d_in[7];
    const float* bo = (const float*)d_in[8];
    float* out = (float*)d_out;

    cudaFuncSetAttribute(setup_kernel, cudaFuncAttributeMaxDynamicSharedMemorySize,
                         SETUP_SMEM_BYTES);
    setup_kernel<<<dim3(8, 8, 3), 256, SETUP_SMEM_BYTES>>>(Wq, Wk, Wv, Wo, bq, bk, bv, bo);

    cudaFuncSetAttribute(attn_kernel, cudaFuncAttributeMaxDynamicSharedMemorySize, SMEM_BYTES);
    attn_kernel<<<2048, 256, SMEM_BYTES>>>(x, out);
}

// round 15
// speedup vs baseline: 1.0509x; 1.0509x over previous
#include <cuda_runtime.h>
#include <cuda_bf16.h>
#include <cstdint>

// AttentionBlock fused kernel, sm_103a. Round 14:
// R11 base (bf16 everywhere, fragment-order weights from L2, 2 CTAs/SM,
// 5 barriers) + uint4 weight fragments: one LDG.128 feeds two n8 mma tiles,
// halving weight LDG instruction count.

#define CH    256
#define LDH   264   // bf16 tile row stride in halves
#define LDP   72    // bf16 P tile stride
#define LDSS  68    // fp32 score stride

// Fused weights in uint4 fragment order: one uint4 per lane per (n16, k16)
// tile; idx = (n16*16 + k16)*32 + lane. Components: (x,y) = n8 tile 0 regs
// (b0,b1), (z,w) = n8 tile 1.
__device__ uint4 g_M8f[16 * 16 * 32];   // Wq @ Wk^T  (k = a-dim, n = b-dim)
__device__ uint4 g_W9f[16 * 16 * 32];   // Wv @ Wo
__device__ float g_b9[CH];              // bv @ Wo + bo
__device__ float g_w8[CH];              // Wk @ bq
__device__ float g_s8;                  // bk . bq

// Dynamic smem: As [32][256] fp32 + Bs [256][33] fp32
#define SETUP_SMEM_FLOATS (8192 + 8448)
#define SETUP_SMEM_BYTES  (SETUP_SMEM_FLOATS * 4)

__global__ void setup_kernel(const float* __restrict__ Wq, const float* __restrict__ Wk,
                             const float* __restrict__ Wv, const float* __restrict__ Wo,
                             const float* __restrict__ bq, const float* __restrict__ bk,
                             const float* __restrict__ bv, const float* __restrict__ bo) {
    extern __shared__ float sdyn[];
    const int tid = threadIdx.x;
    const int z = blockIdx.z;

    if (z == 2) {
        const int id = blockIdx.y * 8 + blockIdx.x;
        if (id < 8) {
            int r = id * 32 + (tid >> 3);
            int q = tid & 7;
            const float4* wk = (const float4*)(Wk + r * CH + q * 32);
            float s = 0.f;
            #pragma unroll
            for (int j = 0; j < 8; j++) {
                float4 v = wk[j];
                int d = q * 32 + j * 4;
                s += v.x * bq[d] + v.y * bq[d + 1] + v.z * bq[d + 2] + v.w * bq[d + 3];
            }
            s += __shfl_xor_sync(0xffffffffu, s, 1);
            s += __shfl_xor_sync(0xffffffffu, s, 2);
            s += __shfl_xor_sync(0xffffffffu, s, 4);
            if (q == 0) g_w8[r] = s;
        } else if (id == 8) {
            float p = bk[tid] * bq[tid];
            #pragma unroll
            for (int d = 16; d > 0; d >>= 1) p += __shfl_xor_sync(0xffffffffu, p, d);
            if ((tid & 31) == 0) sdyn[tid >> 5] = p;
            __syncthreads();
            if (tid == 0) {
                float s = 0.f;
                #pragma unroll
                for (int w = 0; w < 8; w++) s += sdyn[w];
                g_s8 = s;
            }
        } else if (id >= 16 && id < 24) {
            int c0 = (id - 16) * 32;
            int tx = tid & 31, ty = tid >> 5;
            int c = c0 + tx;
            float s = 0.f;
            #pragma unroll 8
            for (int i = 0; i < 32; i++) {
                int d = ty + 8 * i;
                s += bv[d] * Wo[d * CH + c];
            }
            sdyn[ty * 33 + tx] = s;
            __syncthreads();
            if (ty == 0) {
                float t = 0.f;
                #pragma unroll
                for (int w = 0; w < 8; w++) t += sdyn[w * 33 + tx];
                g_b9[c] = t + bo[c];
            }
        }
        return;
    }

    float* As = sdyn;              // [32][256]
    float* Bs = sdyn + 8192;       // [256][33]
    const int tx = tid & 31, ty = tid >> 5;
    const int a0 = blockIdx.y * 32, b0 = blockIdx.x * 32;
    const float* A = z ? Wv : Wq;

    #pragma unroll
    for (int k = 0; k < 8; k++) {
        int idx = tid + k * 256;
        int i = idx >> 6, j = (idx & 63) * 4;
        float4 v = *(const float4*)(A + (a0 + i) * CH + j);
        As[i * 256 + j] = v.x; As[i * 256 + j + 1] = v.y;
        As[i * 256 + j + 2] = v.z; As[i * 256 + j + 3] = v.w;
    }
    if (z == 0) {
        #pragma unroll
        for (int k = 0; k < 8; k++) {
            int idx = tid + k * 256;
            int i = idx >> 6, j = (idx & 63) * 4;
            float4 v = *(const float4*)(Wk + (b0 + i) * CH + j);
            Bs[j * 33 + i] = v.x; Bs[(j + 1) * 33 + i] = v.y;
            Bs[(j + 2) * 33 + i] = v.z; Bs[(j + 3) * 33 + i] = v.w;
        }
    } else {
        #pragma unroll
        for (int k = 0; k < 8; k++) {
            int idx = tid + k * 256;
            int j = idx >> 3, i4 = (idx & 7) * 4;
            float4 v = *(const float4*)(Wo + j * CH + b0 + i4);
            Bs[j * 33 + i4] = v.x; Bs[j * 33 + i4 + 1] = v.y;
            Bs[j * 33 + i4 + 2] = v.z; Bs[j * 33 + i4 + 3] = v.w;
        }
    }
    __syncthreads();

    float acc[4] = {0.f, 0.f, 0.f, 0.f};
    #pragma unroll 4
    for (int dd = 0; dd < 256; dd++) {
        float b = Bs[dd * 33 + tx];
        #pragma unroll
        for (int r = 0; r < 4; r++) acc[r] += As[(ty + 8 * r) * 256 + dd] * b;
    }

    __nv_bfloat16* dst = (__nv_bfloat16*)(z ? g_W9f : g_M8f);
    #pragma unroll
    for (int r = 0; r < 4; r++) {
        int a = a0 + ty + 8 * r;      // k-dim
        int b = b0 + tx;              // n-dim
        // uint4 fragment layout: tile (b>>4, a>>4), lane = (b&7)*4 + ((a&7)>>1),
        // component = ((b>>3)&1)*2 + ((a>>3)&1), halfword = a&1
        int idx = ((((b >> 4) * 16 + (a >> 4)) * 32) + (b & 7) * 4 + ((a & 7) >> 1)) * 8
                + ((b >> 3) & 1) * 4 + ((a >> 3) & 1) * 2 + (a & 1);
        dst[idx] = __float2bfloat16(acc[r]);
    }
}

// ---- mma.sync helpers ----
__device__ __forceinline__ uint32_t smem_u32(const void* p) {
    return (uint32_t)__cvta_generic_to_shared(p);
}
__device__ __forceinline__ void ldm_x4(uint32_t addr, uint32_t& a0, uint32_t& a1,
                                       uint32_t& a2, uint32_t& a3) {
    asm volatile("ldmatrix.sync.aligned.m8n8.x4.shared.b16 {%0,%1,%2,%3}, [%4];"
                 : "=r"(a0), "=r"(a1), "=r"(a2), "=r"(a3) : "r"(addr));
}
__device__ __forceinline__ void ldm_x4t(uint32_t addr, uint32_t& b0, uint32_t& b1,
                                        uint32_t& b2, uint32_t& b3) {
    asm volatile("ldmatrix.sync.aligned.m8n8.x4.trans.shared.b16 {%0,%1,%2,%3}, [%4];"
                 : "=r"(b0), "=r"(b1), "=r"(b2), "=r"(b3) : "r"(addr));
}
__device__ __forceinline__ void mma_bf16(float c[4],
                                         uint32_t a0, uint32_t a1, uint32_t a2, uint32_t a3,
                                         uint32_t b0, uint32_t b1) {
    asm volatile("mma.sync.aligned.m16n8k16.row.col.f32.bf16.bf16.f32 "
                 "{%0,%1,%2,%3}, {%4,%5,%6,%7}, {%8,%9}, {%0,%1,%2,%3};"
                 : "+f"(c[0]), "+f"(c[1]), "+f"(c[2]), "+f"(c[3])
                 : "r"(a0), "r"(a1), "r"(a2), "r"(a3), "r"(b0), "r"(b1));
}

// GEMM, B from L2 uint4 fragments (one LDG.128 = two n8 tiles) with prefetch.
__device__ __forceinline__ void gemm_f(const uint4* __restrict__ Wf,
                                       const __nv_bfloat16* sA,
                                       float acc[2][8][4],
                                       int lane, int r0, int nb) {
    #pragma unroll
    for (int mt = 0; mt < 2; mt++)
        #pragma unroll
        for (int nt = 0; nt < 8; nt++)
            acc[mt][nt][0] = acc[mt][nt][1] = acc[mt][nt][2] = acc[mt][nt][3] = 0.f;

    const uint4* wb = Wf + ((nb >> 4) * 16) * 32 + lane;
    uint4 vc[4], vn[4];
    #pragma unroll
    for (int nt16 = 0; nt16 < 4; nt16++) vc[nt16] = wb[(nt16 * 16) * 32];

    #pragma unroll
    for (int ks = 0; ks < 16; ks++) {
        if (ks < 15) {
            #pragma unroll
            for (int nt16 = 0; nt16 < 4; nt16++) vn[nt16] = wb[(nt16 * 16 + ks + 1) * 32];
        }
        uint32_t a[2][4];
        #pragma unroll
        for (int mt = 0; mt < 2; mt++)
            ldm_x4(smem_u32(sA + (r0 + mt * 16 + (lane & 15)) * LDH
                            + ks * 16 + ((lane >> 4) << 3)),
                   a[mt][0], a[mt][1], a[mt][2], a[mt][3]);
        #pragma unroll
        for (int nt16 = 0; nt16 < 4; nt16++) {
            #pragma unroll
            for (int mt = 0; mt < 2; mt++) {
                mma_bf16(acc[mt][2 * nt16],     a[mt][0], a[mt][1], a[mt][2], a[mt][3],
                         vc[nt16].x, vc[nt16].y);
                mma_bf16(acc[mt][2 * nt16 + 1], a[mt][0], a[mt][1], a[mt][2], a[mt][3],
                         vc[nt16].z, vc[nt16].w);
            }
        }
        if (ks < 15) {
            #pragma unroll
            for (int nt16 = 0; nt16 < 4; nt16++) vc[nt16] = vn[nt16];
        }
    }
}

// SMEM: sX 33792 + sG 33792 + sT 33792 + sP 9216 + sC 256 + sBias 1024 = 111872
#define SMEM_BYTES 111872

__global__ void __launch_bounds__(256, 2)
attn_kernel(const float* __restrict__ x, float* __restrict__ out)
{
    extern __shared__ char smem_raw[];
    __nv_bfloat16* sX  = (__nv_bfloat16*)smem_raw;           // [64][LDH]
    __nv_bfloat16* sG  = sX + 64 * LDH;                      // [64][LDH]
    __nv_bfloat16* sT  = sG + 64 * LDH;                      // [64][LDH]; scores overlay
    float*         sS  = (float*)sT;                         // [64][LDSS] fp32 scores
    __nv_bfloat16* sP  = sT + 64 * LDH;                      // [64][LDP]
    float*         sC  = (float*)(sP + 64 * LDP);            // [64]
    float*      sBias  = sC + 64;                            // [256]

    const int tid  = threadIdx.x;
    const int wid  = tid >> 5;
    const int lane = tid & 31;
    const int grp  = lane >> 2;
    const int tig  = lane & 3;

    const size_t base = (size_t)blockIdx.x * 64 * CH;
    const float* xrow = x   + base;
    float*       orow = out + base;

    // ---------------- Phase 0: bias + x tile (fp32 -> bf16) ----------------
    sBias[tid] = g_b9[tid];
    {
        const float4* xv = (const float4*)xrow;
        #pragma unroll
        for (int t = 0; t < 16; t++) {
            int i = tid + t * 256;
            int row = i >> 6;
            int colf = (i & 63) * 4;
            float4 v = xv[i];
            __nv_bfloat162* d = (__nv_bfloat162*)(sX + row * LDH + colf);
            d[0] = __floats2bfloat162_rn(v.x, v.y);
            d[1] = __floats2bfloat162_rn(v.z, v.w);
        }
    }
    __syncthreads();

    // c_j = x_j . w8 + s8 from sX (bf16; 4 threads per row)
    {
        int row = tid >> 2, q = tid & 3;
        const __nv_bfloat162* xr = (const __nv_bfloat162*)(sX + row * LDH + q * 64);
        float s = 0.f;
        #pragma unroll
        for (int j = 0; j < 32; j++) {
            float2 v = __bfloat1622float2(xr[j]);
            int c = q * 64 + j * 2;
            s += v.x * g_w8[c] + v.y * g_w8[c + 1];
        }
        s += __shfl_xor_sync(0xffffffffu, s, 1);
        s += __shfl_xor_sync(0xffffffffu, s, 2);
        if (q == 0) sC[row] = s + g_s8;
    }
    // sC consumed after the post-G barrier

    const int r0 = (wid >> 2) * 32;   // warp's 32 rows (weight gemms)
    const int nb = (wid & 3) * 64;    // warp's 64 cols

    float acc[2][8][4];

    // ---------------- G = X @ M8 -> sG ----------------
    gemm_f(g_M8f, sX, acc, lane, r0, nb);
    #pragma unroll
    for (int mt = 0; mt < 2; mt++)
        #pragma unroll
        for (int nt = 0; nt < 8; nt++) {
            int col = nb + nt * 8 + tig * 2;
            int ra = r0 + mt * 16 + grp;
            *(__nv_bfloat162*)(sG + ra * LDH + col) =
                __floats2bfloat162_rn(acc[mt][nt][0], acc[mt][nt][1]);
            *(__nv_bfloat162*)(sG + (ra + 8) * LDH + col) =
                __floats2bfloat162_rn(acc[mt][nt][2], acc[mt][nt][3]);
        }
    __syncthreads();

    // ------- S = (G X^T + c_j)*scale -> sS (fp32), ALL 8 warps -------
    {
        const int r0s = (wid & 3) * 16;   // 16 rows
        const int j0  = (wid >> 2) * 32;  // 32 cols
        float sa[4][4];
        #pragma unroll
        for (int nt = 0; nt < 4; nt++)
            sa[nt][0] = sa[nt][1] = sa[nt][2] = sa[nt][3] = 0.f;
        #pragma unroll
        for (int ks = 0; ks < 16; ks++) {
            uint32_t a0, a1, a2, a3;
            ldm_x4(smem_u32(sG + (r0s + (lane & 15)) * LDH + ks * 16 + ((lane >> 4) << 3)),
                   a0, a1, a2, a3);
            uint32_t b0, b1, b2, b3;
            ldm_x4(smem_u32(sX + (j0 + ((lane >> 4) << 3) + (lane & 7)) * LDH
                            + ks * 16 + (((lane >> 3) & 1) << 3)),
                   b0, b1, b2, b3);
            mma_bf16(sa[0], a0, a1, a2, a3, b0, b1);
            mma_bf16(sa[1], a0, a1, a2, a3, b2, b3);
            uint32_t c0, c1, c2, c3;
            ldm_x4(smem_u32(sX + (j0 + 16 + ((lane >> 4) << 3) + (lane & 7)) * LDH
                            + ks * 16 + (((lane >> 3) & 1) << 3)),
                   c0, c1, c2, c3);
            mma_bf16(sa[2], a0, a1, a2, a3, c0, c1);
            mma_bf16(sa[3], a0, a1, a2, a3, c2, c3);
        }
        const float SCALE = 1.0f / (256.0f * 16.0f * 0.70710678118654752f);
        #pragma unroll
        for (int nt = 0; nt < 4; nt++) {
            int col = j0 + nt * 8 + tig * 2;
            float c0 = sC[col], c1 = sC[col + 1];
            sS[(r0s + grp) * LDSS + col]         = (sa[nt][0] + c0) * SCALE;
            sS[(r0s + grp) * LDSS + col + 1]     = (sa[nt][1] + c1) * SCALE;
            sS[(r0s + grp + 8) * LDSS + col]     = (sa[nt][2] + c0) * SCALE;
            sS[(r0s + grp + 8) * LDSS + col + 1] = (sa[nt][3] + c1) * SCALE;
        }
    }
    __syncthreads();

    // ---------------- softmax rows -> P (bf16); 4 threads/row ----------------
    {
        int row = tid >> 2, t4 = tid & 3;
        const float* sr = sS + row * LDSS + t4 * 16;
        float v[16];
        #pragma unroll
        for (int i = 0; i < 16; i++) v[i] = sr[i];
        float m = v[0];
        #pragma unroll
        for (int i = 1; i < 16; i++) m = fmaxf(m, v[i]);
        m = fmaxf(m, __shfl_xor_sync(0xffffffffu, m, 1));
        m = fmaxf(m, __shfl_xor_sync(0xffffffffu, m, 2));
        float s = 0.f;
        #pragma unroll
        for (int i = 0; i < 16; i++) { v[i] = __expf(v[i] - m); s += v[i]; }
        s += __shfl_xor_sync(0xffffffffu, s, 1);
        s += __shfl_xor_sync(0xffffffffu, s, 2);
        float inv = 1.0f / s;
        __nv_bfloat162* dp = (__nv_bfloat162*)(sP + row * LDP + t4 * 16);
        #pragma unroll
        for (int i = 0; i < 8; i++)
            dp[i] = __floats2bfloat162_rn(v[2 * i] * inv, v[2 * i + 1] * inv);
    }
    __syncthreads();

    // ---------------- T = P @ X -> sT (scores dead) ----------------
    {
        #pragma unroll
        for (int mt = 0; mt < 2; mt++)
            #pragma unroll
            for (int nt = 0; nt < 8; nt++)
                acc[mt][nt][0] = acc[mt][nt][1] = acc[mt][nt][2] = acc[mt][nt][3] = 0.f;
        #pragma unroll
        for (int ks = 0; ks < 4; ks++) {
            uint32_t a[2][4];
            #pragma unroll
            for (int mt = 0; mt < 2; mt++)
                ldm_x4(smem_u32(sP + (r0 + mt * 16 + (lane & 15)) * LDP
                                + ks * 16 + ((lane >> 4) << 3)),
                       a[mt][0], a[mt][1], a[mt][2], a[mt][3]);
            #pragma unroll
            for (int nt16 = 0; nt16 < 4; nt16++) {
                uint32_t b0, b1, b2, b3;
                ldm_x4t(smem_u32(sX + (ks * 16 + (lane & 15)) * LDH
                                 + nb + nt16 * 16 + ((lane >> 4) << 3)),
                        b0, b1, b2, b3);
                #pragma unroll
                for (int mt = 0; mt < 2; mt++) {
                    mma_bf16(acc[mt][2 * nt16],     a[mt][0], a[mt][1], a[mt][2], a[mt][3], b0, b1);
                    mma_bf16(acc[mt][2 * nt16 + 1], a[mt][0], a[mt][1], a[mt][2], a[mt][3], b2, b3);
                }
            }
        }
        #pragma unroll
        for (int mt = 0; mt < 2; mt++)
            #pragma unroll
            for (int nt = 0; nt < 8; nt++) {
                int col = nb + nt * 8 + tig * 2;
                int ra = r0 + mt * 16 + grp;
                *(__nv_bfloat162*)(sT + ra * LDH + col) =
                    __floats2bfloat162_rn(acc[mt][nt][0], acc[mt][nt][1]);
                *(__nv_bfloat162*)(sT + (ra + 8) * LDH + col) =
                    __floats2bfloat162_rn(acc[mt][nt][2], acc[mt][nt][3]);
            }
    }
    __syncthreads();

    // ---------------- out = T @ W9 + b9 + x ----------------
    gemm_f(g_W9f, sT, acc, lane, r0, nb);
    #pragma unroll
    for (int mt = 0; mt < 2; mt++)
        #pragma unroll
        for (int nt = 0; nt < 8; nt++) {
            int col = nb + nt * 8 + tig * 2;
            float b0v = sBias[col], b1v = sBias[col + 1];
            int ra = r0 + mt * 16 + grp, rb = ra + 8;
            float2 xa = *(const float2*)(xrow + ra * CH + col);
            float2 xb = *(const float2*)(xrow + rb * CH + col);
            *(float2*)(orow + ra * CH + col) =
                make_float2(acc[mt][nt][0] + b0v + xa.x, acc[mt][nt][1] + b1v + xa.y);
            *(float2*)(orow + rb * CH + col) =
                make_float2(acc[mt][nt][2] + b0v + xb.x, acc[mt][nt][3] + b1v + xb.y);
        }
}

extern "C" void kernel_launch(void* const* d_in, const int* in_sizes, int n_in,
                              void* d_out, int out_size) {
    const float* x  = (const float*)d_in[0];
    const float* Wq = (const float*)d_in[1];
    const float* bq = (const float*)d_in[2];
    const float* Wk = (const float*)d_in[3];
    const float* bk = (const float*)d_in[4];
    const float* Wv = (const float*)d_in[5];
    const float* bv = (const float*)d_in[6];
    const float* Wo = (const float*)d_in[7];
    const float* bo = (const float*)d_in[8];
    float* out = (float*)d_out;

    cudaFuncSetAttribute(setup_kernel, cudaFuncAttributeMaxDynamicSharedMemorySize,
                         SETUP_SMEM_BYTES);
    setup_kernel<<<dim3(8, 8, 3), 256, SETUP_SMEM_BYTES>>>(Wq, Wk, Wv, Wo, bq, bk, bv, bo);

    cudaFuncSetAttribute(attn_kernel, cudaFuncAttributeMaxDynamicSharedMemorySize, SMEM_BYTES);
    attn_kernel<<<2048, 256, SMEM_BYTES>>>(x, out);
}

// round 16
// speedup vs baseline: 1.0781x; 1.0258x over previous
#include <cuda_runtime.h>
#include <cuda_bf16.h>
#include <cstdint>

// AttentionBlock fused kernel, sm_103a. Round 15:
// Re-associated output GEMM: Y = X@W9 computed WITH G = X@M8 in one fused
// dual-GEMM phase (2x ILP in the weight-latency window); after softmax only
// out = P@Y (K=64, smem operands). Scores stored bf16 in-place in sP.
// 4 block barriers, 2 CTAs/SM, uint4 weight fragments from L2.

#define CH    256
#define LDH   264   // bf16 tile row stride in halves
#define LDP   72    // bf16 P tile stride

// Fused weights in uint4 fragment order: one uint4 per lane per (n16, k16)
// tile; idx = (n16*16 + k16)*32 + lane. (x,y) = n8 tile 0, (z,w) = n8 tile 1.
__device__ uint4 g_M8f[16 * 16 * 32];   // Wq @ Wk^T  (k = a-dim, n = b-dim)
__device__ uint4 g_W9f[16 * 16 * 32];   // Wv @ Wo
__device__ float g_b9[CH];              // bv @ Wo + bo
__device__ float g_w8[CH];              // Wk @ bq
__device__ float g_s8;                  // bk . bq

// Dynamic smem: As [32][256] fp32 + Bs [256][33] fp32
#define SETUP_SMEM_FLOATS (8192 + 8448)
#define SETUP_SMEM_BYTES  (SETUP_SMEM_FLOATS * 4)

__global__ void setup_kernel(const float* __restrict__ Wq, const float* __restrict__ Wk,
                             const float* __restrict__ Wv, const float* __restrict__ Wo,
                             const float* __restrict__ bq, const float* __restrict__ bk,
                             const float* __restrict__ bv, const float* __restrict__ bo) {
    extern __shared__ float sdyn[];
    const int tid = threadIdx.x;
    const int z = blockIdx.z;

    if (z == 2) {
        const int id = blockIdx.y * 8 + blockIdx.x;
        if (id < 8) {
            int r = id * 32 + (tid >> 3);
            int q = tid & 7;
            const float4* wk = (const float4*)(Wk + r * CH + q * 32);
            float s = 0.f;
            #pragma unroll
            for (int j = 0; j < 8; j++) {
                float4 v = wk[j];
                int d = q * 32 + j * 4;
                s += v.x * bq[d] + v.y * bq[d + 1] + v.z * bq[d + 2] + v.w * bq[d + 3];
            }
            s += __shfl_xor_sync(0xffffffffu, s, 1);
            s += __shfl_xor_sync(0xffffffffu, s, 2);
            s += __shfl_xor_sync(0xffffffffu, s, 4);
            if (q == 0) g_w8[r] = s;
        } else if (id == 8) {
            float p = bk[tid] * bq[tid];
            #pragma unroll
            for (int d = 16; d > 0; d >>= 1) p += __shfl_xor_sync(0xffffffffu, p, d);
            if ((tid & 31) == 0) sdyn[tid >> 5] = p;
            __syncthreads();
            if (tid == 0) {
                float s = 0.f;
                #pragma unroll
                for (int w = 0; w < 8; w++) s += sdyn[w];
                g_s8 = s;
            }
        } else if (id >= 16 && id < 24) {
            int c0 = (id - 16) * 32;
            int tx = tid & 31, ty = tid >> 5;
            int c = c0 + tx;
            float s = 0.f;
            #pragma unroll 8
            for (int i = 0; i < 32; i++) {
                int d = ty + 8 * i;
                s += bv[d] * Wo[d * CH + c];
            }
            sdyn[ty * 33 + tx] = s;
            __syncthreads();
            if (ty == 0) {
                float t = 0.f;
                #pragma unroll
                for (int w = 0; w < 8; w++) t += sdyn[w * 33 + tx];
                g_b9[c] = t + bo[c];
            }
        }
        return;
    }

    float* As = sdyn;              // [32][256]
    float* Bs = sdyn + 8192;       // [256][33]
    const int tx = tid & 31, ty = tid >> 5;
    const int a0 = blockIdx.y * 32, b0 = blockIdx.x * 32;
    const float* A = z ? Wv : Wq;

    #pragma unroll
    for (int k = 0; k < 8; k++) {
        int idx = tid + k * 256;
        int i = idx >> 6, j = (idx & 63) * 4;
        float4 v = *(const float4*)(A + (a0 + i) * CH + j);
        As[i * 256 + j] = v.x; As[i * 256 + j + 1] = v.y;
        As[i * 256 + j + 2] = v.z; As[i * 256 + j + 3] = v.w;
    }
    if (z == 0) {
        #pragma unroll
        for (int k = 0; k < 8; k++) {
            int idx = tid + k * 256;
            int i = idx >> 6, j = (idx & 63) * 4;
            float4 v = *(const float4*)(Wk + (b0 + i) * CH + j);
            Bs[j * 33 + i] = v.x; Bs[(j + 1) * 33 + i] = v.y;
            Bs[(j + 2) * 33 + i] = v.z; Bs[(j + 3) * 33 + i] = v.w;
        }
    } else {
        #pragma unroll
        for (int k = 0; k < 8; k++) {
            int idx = tid + k * 256;
            int j = idx >> 3, i4 = (idx & 7) * 4;
            float4 v = *(const float4*)(Wo + j * CH + b0 + i4);
            Bs[j * 33 + i4] = v.x; Bs[j * 33 + i4 + 1] = v.y;
            Bs[j * 33 + i4 + 2] = v.z; Bs[j * 33 + i4 + 3] = v.w;
        }
    }
    __syncthreads();

    float acc[4] = {0.f, 0.f, 0.f, 0.f};
    #pragma unroll 4
    for (int dd = 0; dd < 256; dd++) {
        float b = Bs[dd * 33 + tx];
        #pragma unroll
        for (int r = 0; r < 4; r++) acc[r] += As[(ty + 8 * r) * 256 + dd] * b;
    }

    __nv_bfloat16* dst = (__nv_bfloat16*)(z ? g_W9f : g_M8f);
    #pragma unroll
    for (int r = 0; r < 4; r++) {
        int a = a0 + ty + 8 * r;      // k-dim
        int b = b0 + tx;              // n-dim
        int idx = ((((b >> 4) * 16 + (a >> 4)) * 32) + (b & 7) * 4 + ((a & 7) >> 1)) * 8
                + ((b >> 3) & 1) * 4 + ((a >> 3) & 1) * 2 + (a & 1);
        dst[idx] = __float2bfloat16(acc[r]);
    }
}

// ---- mma.sync helpers ----
__device__ __forceinline__ uint32_t smem_u32(const void* p) {
    return (uint32_t)__cvta_generic_to_shared(p);
}
__device__ __forceinline__ void ldm_x4(uint32_t addr, uint32_t& a0, uint32_t& a1,
                                       uint32_t& a2, uint32_t& a3) {
    asm volatile("ldmatrix.sync.aligned.m8n8.x4.shared.b16 {%0,%1,%2,%3}, [%4];"
                 : "=r"(a0), "=r"(a1), "=r"(a2), "=r"(a3) : "r"(addr));
}
__device__ __forceinline__ void ldm_x4t(uint32_t addr, uint32_t& b0, uint32_t& b1,
                                        uint32_t& b2, uint32_t& b3) {
    asm volatile("ldmatrix.sync.aligned.m8n8.x4.trans.shared.b16 {%0,%1,%2,%3}, [%4];"
                 : "=r"(b0), "=r"(b1), "=r"(b2), "=r"(b3) : "r"(addr));
}
__device__ __forceinline__ void mma_bf16(float c[4],
                                         uint32_t a0, uint32_t a1, uint32_t a2, uint32_t a3,
                                         uint32_t b0, uint32_t b1) {
    asm volatile("mma.sync.aligned.m16n8k16.row.col.f32.bf16.bf16.f32 "
                 "{%0,%1,%2,%3}, {%4,%5,%6,%7}, {%8,%9}, {%0,%1,%2,%3};"
                 : "+f"(c[0]), "+f"(c[1]), "+f"(c[2]), "+f"(c[3])
                 : "r"(a0), "r"(a1), "r"(a2), "r"(a3), "r"(b0), "r"(b1));
}

// GEMM, B from L2 uint4 fragments (one LDG.128 = two n8 tiles) with prefetch.
__device__ __forceinline__ void gemm_f(const uint4* __restrict__ Wf,
                                       const __nv_bfloat16* sA,
                                       float acc[2][8][4],
                                       int lane, int r0, int nb) {
    #pragma unroll
    for (int mt = 0; mt < 2; mt++)
        #pragma unroll
        for (int nt = 0; nt < 8; nt++)
            acc[mt][nt][0] = acc[mt][nt][1] = acc[mt][nt][2] = acc[mt][nt][3] = 0.f;

    const uint4* wb = Wf + ((nb >> 4) * 16) * 32 + lane;
    uint4 vc[4], vn[4];
    #pragma unroll
    for (int nt16 = 0; nt16 < 4; nt16++) vc[nt16] = wb[(nt16 * 16) * 32];

    #pragma unroll
    for (int ks = 0; ks < 16; ks++) {
        if (ks < 15) {
            #pragma unroll
            for (int nt16 = 0; nt16 < 4; nt16++) vn[nt16] = wb[(nt16 * 16 + ks + 1) * 32];
        }
        uint32_t a[2][4];
        #pragma unroll
        for (int mt = 0; mt < 2; mt++)
            ldm_x4(smem_u32(sA + (r0 + mt * 16 + (lane & 15)) * LDH
                            + ks * 16 + ((lane >> 4) << 3)),
                   a[mt][0], a[mt][1], a[mt][2], a[mt][3]);
        #pragma unroll
        for (int nt16 = 0; nt16 < 4; nt16++) {
            #pragma unroll
            for (int mt = 0; mt < 2; mt++) {
                mma_bf16(acc[mt][2 * nt16],     a[mt][0], a[mt][1], a[mt][2], a[mt][3],
                         vc[nt16].x, vc[nt16].y);
                mma_bf16(acc[mt][2 * nt16 + 1], a[mt][0], a[mt][1], a[mt][2], a[mt][3],
                         vc[nt16].z, vc[nt16].w);
            }
        }
        if (ks < 15) {
            #pragma unroll
            for (int nt16 = 0; nt16 < 4; nt16++) vc[nt16] = vn[nt16];
        }
    }
}

// Store a 32x64 warp-tile accumulator into a bf16 [64][LDH] buffer.
__device__ __forceinline__ void store_tile(__nv_bfloat16* dst, float acc[2][8][4],
                                           int r0, int nb, int grp, int tig) {
    #pragma unroll
    for (int mt = 0; mt < 2; mt++)
        #pragma unroll
        for (int nt = 0; nt < 8; nt++) {
            int col = nb + nt * 8 + tig * 2;
            int ra = r0 + mt * 16 + grp;
            *(__nv_bfloat162*)(dst + ra * LDH + col) =
                __floats2bfloat162_rn(acc[mt][nt][0], acc[mt][nt][1]);
            *(__nv_bfloat162*)(dst + (ra + 8) * LDH + col) =
                __floats2bfloat162_rn(acc[mt][nt][2], acc[mt][nt][3]);
        }
}

// SMEM: sX 33792 + sG 33792 + sY 33792 + sP 9216 + sC 256 + sBias 1024 = 111872
#define SMEM_BYTES 111872

__global__ void __launch_bounds__(256, 2)
attn_kernel(const float* __restrict__ x, float* __restrict__ out)
{
    extern __shared__ char smem_raw[];
    __nv_bfloat16* sX  = (__nv_bfloat16*)smem_raw;           // [64][LDH]
    __nv_bfloat16* sG  = sX + 64 * LDH;                      // [64][LDH]
    __nv_bfloat16* sY  = sG + 64 * LDH;                      // [64][LDH]  Y = X@W9
    __nv_bfloat16* sP  = sY + 64 * LDH;                      // [64][LDP]  scores -> P
    float*         sC  = (float*)(sP + 64 * LDP);            // [64]
    float*      sBias  = sC + 64;                            // [256]

    const int tid  = threadIdx.x;
    const int wid  = tid >> 5;
    const int lane = tid & 31;
    const int grp  = lane >> 2;
    const int tig  = lane & 3;

    const size_t base = (size_t)blockIdx.x * 64 * CH;
    const float* xrow = x   + base;
    float*       orow = out + base;

    // ---------------- Phase 0: bias + x tile (fp32 -> bf16) ----------------
    sBias[tid] = g_b9[tid];
    {
        const float4* xv = (const float4*)xrow;
        #pragma unroll
        for (int t = 0; t < 16; t++) {
            int i = tid + t * 256;
            int row = i >> 6;
            int colf = (i & 63) * 4;
            float4 v = xv[i];
            __nv_bfloat162* d = (__nv_bfloat162*)(sX + row * LDH + colf);
            d[0] = __floats2bfloat162_rn(v.x, v.y);
            d[1] = __floats2bfloat162_rn(v.z, v.w);
        }
    }
    __syncthreads();

    // c_j = x_j . w8 + s8 from sX (bf16; 4 threads per row)
    {
        int row = tid >> 2, q = tid & 3;
        const __nv_bfloat162* xr = (const __nv_bfloat162*)(sX + row * LDH + q * 64);
        float s = 0.f;
        #pragma unroll
        for (int j = 0; j < 32; j++) {
            float2 v = __bfloat1622float2(xr[j]);
            int c = q * 64 + j * 2;
            s += v.x * g_w8[c] + v.y * g_w8[c + 1];
        }
        s += __shfl_xor_sync(0xffffffffu, s, 1);
        s += __shfl_xor_sync(0xffffffffu, s, 2);
        if (q == 0) sC[row] = s + g_s8;
    }
    // sC consumed after the next barrier

    const int r0 = (wid >> 2) * 32;   // warp's 32 rows (weight gemms)
    const int nb = (wid & 3) * 64;    // warp's 64 cols

    float acc[2][8][4];

    // ------- Phase 1: dual GEMM, no intervening barrier -------
    // G = X @ M8 -> sG
    gemm_f(g_M8f, sX, acc, lane, r0, nb);
    store_tile(sG, acc, r0, nb, grp, tig);
    // Y = X @ W9 -> sY (independent of G; back-to-back mma/prefetch stream)
    gemm_f(g_W9f, sX, acc, lane, r0, nb);
    store_tile(sY, acc, r0, nb, grp, tig);
    __syncthreads();

    // ------- Phase 2: S = (G X^T + c_j)*scale -> sP (bf16), ALL 8 warps -------
    {
        const int r0s = (wid & 3) * 16;   // 16 rows
        const int j0  = (wid >> 2) * 32;  // 32 cols
        float sa[4][4];
        #pragma unroll
        for (int nt = 0; nt < 4; nt++)
            sa[nt][0] = sa[nt][1] = sa[nt][2] = sa[nt][3] = 0.f;
        #pragma unroll
        for (int ks = 0; ks < 16; ks++) {
            uint32_t a0, a1, a2, a3;
            ldm_x4(smem_u32(sG + (r0s + (lane & 15)) * LDH + ks * 16 + ((lane >> 4) << 3)),
                   a0, a1, a2, a3);
            uint32_t b0, b1, b2, b3;
            ldm_x4(smem_u32(sX + (j0 + ((lane >> 4) << 3) + (lane & 7)) * LDH
                            + ks * 16 + (((lane >> 3) & 1) << 3)),
                   b0, b1, b2, b3);
            mma_bf16(sa[0], a0, a1, a2, a3, b0, b1);
            mma_bf16(sa[1], a0, a1, a2, a3, b2, b3);
            uint32_t c0, c1, c2, c3;
            ldm_x4(smem_u32(sX + (j0 + 16 + ((lane >> 4) << 3) + (lane & 7)) * LDH
                            + ks * 16 + (((lane >> 3) & 1) << 3)),
                   c0, c1, c2, c3);
            mma_bf16(sa[2], a0, a1, a2, a3, c0, c1);
            mma_bf16(sa[3], a0, a1, a2, a3, c2, c3);
        }
        const float SCALE = 1.0f / (256.0f * 16.0f * 0.70710678118654752f);
        #pragma unroll
        for (int nt = 0; nt < 4; nt++) {
            int col = j0 + nt * 8 + tig * 2;
            float c0 = sC[col], c1 = sC[col + 1];
            *(__nv_bfloat162*)(sP + (r0s + grp) * LDP + col) =
                __floats2bfloat162_rn((sa[nt][0] + c0) * SCALE, (sa[nt][1] + c1) * SCALE);
            *(__nv_bfloat162*)(sP + (r0s + grp + 8) * LDP + col) =
                __floats2bfloat162_rn((sa[nt][2] + c0) * SCALE, (sa[nt][3] + c1) * SCALE);
        }
    }
    __syncthreads();

    // ------- Phase 3: softmax in place on sP (bf16); 4 threads/row -------
    {
        int row = tid >> 2, t4 = tid & 3;
        __nv_bfloat162* pr = (__nv_bfloat162*)(sP + row * LDP + t4 * 16);
        float v[16];
        #pragma unroll
        for (int i = 0; i < 8; i++) {
            float2 f = __bfloat1622float2(pr[i]);
            v[2 * i] = f.x; v[2 * i + 1] = f.y;
        }
        float m = v[0];
        #pragma unroll
        for (int i = 1; i < 16; i++) m = fmaxf(m, v[i]);
        m = fmaxf(m, __shfl_xor_sync(0xffffffffu, m, 1));
        m = fmaxf(m, __shfl_xor_sync(0xffffffffu, m, 2));
        float s = 0.f;
        #pragma unroll
        for (int i = 0; i < 16; i++) { v[i] = __expf(v[i] - m); s += v[i]; }
        s += __shfl_xor_sync(0xffffffffu, s, 1);
        s += __shfl_xor_sync(0xffffffffu, s, 2);
        float inv = 1.0f / s;
        #pragma unroll
        for (int i = 0; i < 8; i++)
            pr[i] = __floats2bfloat162_rn(v[2 * i] * inv, v[2 * i + 1] * inv);
    }
    __syncthreads();

    // ------- Phase 4: out = P @ Y + b9 + x (K=64, smem operands) -------
    {
        #pragma unroll
        for (int mt = 0; mt < 2; mt++)
            #pragma unroll
            for (int nt = 0; nt < 8; nt++)
                acc[mt][nt][0] = acc[mt][nt][1] = acc[mt][nt][2] = acc[mt][nt][3] = 0.f;
        #pragma unroll
        for (int ks = 0; ks < 4; ks++) {
            uint32_t a[2][4];
            #pragma unroll
            for (int mt = 0; mt < 2; mt++)
                ldm_x4(smem_u32(sP + (r0 + mt * 16 + (lane & 15)) * LDP
                                + ks * 16 + ((lane >> 4) << 3)),
                       a[mt][0], a[mt][1], a[mt][2], a[mt][3]);
            #pragma unroll
            for (int nt16 = 0; nt16 < 4; nt16++) {
                uint32_t b0, b1, b2, b3;
                ldm_x4t(smem_u32(sY + (ks * 16 + (lane & 15)) * LDH
                                 + nb + nt16 * 16 + ((lane >> 4) << 3)),
                        b0, b1, b2, b3);
                #pragma unroll
                for (int mt = 0; mt < 2; mt++) {
                    mma_bf16(acc[mt][2 * nt16],     a[mt][0], a[mt][1], a[mt][2], a[mt][3], b0, b1);
                    mma_bf16(acc[mt][2 * nt16 + 1], a[mt][0], a[mt][1], a[mt][2], a[mt][3], b2, b3);
                }
            }
        }
        #pragma unroll
        for (int mt = 0; mt < 2; mt++)
            #pragma unroll
            for (int nt = 0; nt < 8; nt++) {
                int col = nb + nt * 8 + tig * 2;
                float b0v = sBias[col], b1v = sBias[col + 1];
                int ra = r0 + mt * 16 + grp, rb = ra + 8;
                float2 xa = *(const float2*)(xrow + ra * CH + col);
                float2 xb = *(const float2*)(xrow + rb * CH + col);
                *(float2*)(orow + ra * CH + col) =
                    make_float2(acc[mt][nt][0] + b0v + xa.x, acc[mt][nt][1] + b1v + xa.y);
                *(float2*)(orow + rb * CH + col) =
                    make_float2(acc[mt][nt][2] + b0v + xb.x, acc[mt][nt][3] + b1v + xb.y);
            }
    }
}

extern "C" void kernel_launch(void* const* d_in, const int* in_sizes, int n_in,
                              void* d_out, int out_size) {
    const float* x  = (const float*)d_in[0];
    const float* Wq = (const float*)d_in[1];
    const float* bq = (const float*)d_in[2];
    const float* Wk = (const float*)d_in[3];
    const float* bk = (const float*)d_in[4];
    const float* Wv = (const float*)d_in[5];
    const float* bv = (const float*)d_in[6];
    const float* Wo = (const float*)d_in[7];
    const float* bo = (const float*)d_in[8];
    float* out = (float*)d_out;

    cudaFuncSetAttribute(setup_kernel, cudaFuncAttributeMaxDynamicSharedMemorySize,
                         SETUP_SMEM_BYTES);
    setup_kernel<<<dim3(8, 8, 3), 256, SETUP_SMEM_BYTES>>>(Wq, Wk, Wv, Wo, bq, bk, bv, bo);

    cudaFuncSetAttribute(attn_kernel, cudaFuncAttributeMaxDynamicSharedMemorySize, SMEM_BYTES);
    attn_kernel<<<2048, 256, SMEM_BYTES>>>(x, out);
}

// round 17
// speedup vs baseline: 1.0809x; 1.0027x over previous
#include <cuda_runtime.h>
#include <cuda_bf16.h>
#include <cstdint>

// AttentionBlock fused kernel, sm_103a. Round 16:
// R15 (dual GEMM G,Y = X@{M8,W9}; out = P@Y) with S+softmax fused in-register
// on warps 0-3 (no score smem round-trip, one fewer barrier); warps 4-7
// prefetch the residual x into L2 meanwhile. 3 block barriers, 2 CTAs/SM.

#define CH    256
#define LDH   264   // bf16 tile row stride in halves
#define LDP   72    // bf16 P tile stride

// Fused weights in uint4 fragment order: one uint4 per lane per (n16, k16)
// tile; idx = (n16*16 + k16)*32 + lane. (x,y) = n8 tile 0, (z,w) = n8 tile 1.
__device__ uint4 g_M8f[16 * 16 * 32];   // Wq @ Wk^T  (k = a-dim, n = b-dim)
__device__ uint4 g_W9f[16 * 16 * 32];   // Wv @ Wo
__device__ float g_b9[CH];              // bv @ Wo + bo
__device__ float g_w8[CH];              // Wk @ bq
__device__ float g_s8;                  // bk . bq

// Dynamic smem: As [32][256] fp32 + Bs [256][33] fp32
#define SETUP_SMEM_FLOATS (8192 + 8448)
#define SETUP_SMEM_BYTES  (SETUP_SMEM_FLOATS * 4)

__global__ void setup_kernel(const float* __restrict__ Wq, const float* __restrict__ Wk,
                             const float* __restrict__ Wv, const float* __restrict__ Wo,
                             const float* __restrict__ bq, const float* __restrict__ bk,
                             const float* __restrict__ bv, const float* __restrict__ bo) {
    extern __shared__ float sdyn[];
    const int tid = threadIdx.x;
    const int z = blockIdx.z;

    if (z == 2) {
        const int id = blockIdx.y * 8 + blockIdx.x;
        if (id < 8) {
            int r = id * 32 + (tid >> 3);
            int q = tid & 7;
            const float4* wk = (const float4*)(Wk + r * CH + q * 32);
            float s = 0.f;
            #pragma unroll
            for (int j = 0; j < 8; j++) {
                float4 v = wk[j];
                int d = q * 32 + j * 4;
                s += v.x * bq[d] + v.y * bq[d + 1] + v.z * bq[d + 2] + v.w * bq[d + 3];
            }
            s += __shfl_xor_sync(0xffffffffu, s, 1);
            s += __shfl_xor_sync(0xffffffffu, s, 2);
            s += __shfl_xor_sync(0xffffffffu, s, 4);
            if (q == 0) g_w8[r] = s;
        } else if (id == 8) {
            float p = bk[tid] * bq[tid];
            #pragma unroll
            for (int d = 16; d > 0; d >>= 1) p += __shfl_xor_sync(0xffffffffu, p, d);
            if ((tid & 31) == 0) sdyn[tid >> 5] = p;
            __syncthreads();
            if (tid == 0) {
                float s = 0.f;
                #pragma unroll
                for (int w = 0; w < 8; w++) s += sdyn[w];
                g_s8 = s;
            }
        } else if (id >= 16 && id < 24) {
            int c0 = (id - 16) * 32;
            int tx = tid & 31, ty = tid >> 5;
            int c = c0 + tx;
            float s = 0.f;
            #pragma unroll 8
            for (int i = 0; i < 32; i++) {
                int d = ty + 8 * i;
                s += bv[d] * Wo[d * CH + c];
            }
            sdyn[ty * 33 + tx] = s;
            __syncthreads();
            if (ty == 0) {
                float t = 0.f;
                #pragma unroll
                for (int w = 0; w < 8; w++) t += sdyn[w * 33 + tx];
                g_b9[c] = t + bo[c];
            }
        }
        return;
    }

    float* As = sdyn;              // [32][256]
    float* Bs = sdyn + 8192;       // [256][33]
    const int tx = tid & 31, ty = tid >> 5;
    const int a0 = blockIdx.y * 32, b0 = blockIdx.x * 32;
    const float* A = z ? Wv : Wq;

    #pragma unroll
    for (int k = 0; k < 8; k++) {
        int idx = tid + k * 256;
        int i = idx >> 6, j = (idx & 63) * 4;
        float4 v = *(const float4*)(A + (a0 + i) * CH + j);
        As[i * 256 + j] = v.x; As[i * 256 + j + 1] = v.y;
        As[i * 256 + j + 2] = v.z; As[i * 256 + j + 3] = v.w;
    }
    if (z == 0) {
        #pragma unroll
        for (int k = 0; k < 8; k++) {
            int idx = tid + k * 256;
            int i = idx >> 6, j = (idx & 63) * 4;
            float4 v = *(const float4*)(Wk + (b0 + i) * CH + j);
            Bs[j * 33 + i] = v.x; Bs[(j + 1) * 33 + i] = v.y;
            Bs[(j + 2) * 33 + i] = v.z; Bs[(j + 3) * 33 + i] = v.w;
        }
    } else {
        #pragma unroll
        for (int k = 0; k < 8; k++) {
            int idx = tid + k * 256;
            int j = idx >> 3, i4 = (idx & 7) * 4;
            float4 v = *(const float4*)(Wo + j * CH + b0 + i4);
            Bs[j * 33 + i4] = v.x; Bs[j * 33 + i4 + 1] = v.y;
            Bs[j * 33 + i4 + 2] = v.z; Bs[j * 33 + i4 + 3] = v.w;
        }
    }
    __syncthreads();

    float acc[4] = {0.f, 0.f, 0.f, 0.f};
    #pragma unroll 4
    for (int dd = 0; dd < 256; dd++) {
        float b = Bs[dd * 33 + tx];
        #pragma unroll
        for (int r = 0; r < 4; r++) acc[r] += As[(ty + 8 * r) * 256 + dd] * b;
    }

    __nv_bfloat16* dst = (__nv_bfloat16*)(z ? g_W9f : g_M8f);
    #pragma unroll
    for (int r = 0; r < 4; r++) {
        int a = a0 + ty + 8 * r;      // k-dim
        int b = b0 + tx;              // n-dim
        int idx = ((((b >> 4) * 16 + (a >> 4)) * 32) + (b & 7) * 4 + ((a & 7) >> 1)) * 8
                + ((b >> 3) & 1) * 4 + ((a >> 3) & 1) * 2 + (a & 1);
        dst[idx] = __float2bfloat16(acc[r]);
    }
}

// ---- mma.sync helpers ----
__device__ __forceinline__ uint32_t smem_u32(const void* p) {
    return (uint32_t)__cvta_generic_to_shared(p);
}
__device__ __forceinline__ void ldm_x4(uint32_t addr, uint32_t& a0, uint32_t& a1,
                                       uint32_t& a2, uint32_t& a3) {
    asm volatile("ldmatrix.sync.aligned.m8n8.x4.shared.b16 {%0,%1,%2,%3}, [%4];"
                 : "=r"(a0), "=r"(a1), "=r"(a2), "=r"(a3) : "r"(addr));
}
__device__ __forceinline__ void ldm_x4t(uint32_t addr, uint32_t& b0, uint32_t& b1,
                                        uint32_t& b2, uint32_t& b3) {
    asm volatile("ldmatrix.sync.aligned.m8n8.x4.trans.shared.b16 {%0,%1,%2,%3}, [%4];"
                 : "=r"(b0), "=r"(b1), "=r"(b2), "=r"(b3) : "r"(addr));
}
__device__ __forceinline__ void mma_bf16(float c[4],
                                         uint32_t a0, uint32_t a1, uint32_t a2, uint32_t a3,
                                         uint32_t b0, uint32_t b1) {
    asm volatile("mma.sync.aligned.m16n8k16.row.col.f32.bf16.bf16.f32 "
                 "{%0,%1,%2,%3}, {%4,%5,%6,%7}, {%8,%9}, {%0,%1,%2,%3};"
                 : "+f"(c[0]), "+f"(c[1]), "+f"(c[2]), "+f"(c[3])
                 : "r"(a0), "r"(a1), "r"(a2), "r"(a3), "r"(b0), "r"(b1));
}

// GEMM, B from L2 uint4 fragments (one LDG.128 = two n8 tiles) with prefetch.
__device__ __forceinline__ void gemm_f(const uint4* __restrict__ Wf,
                                       const __nv_bfloat16* sA,
                                       float acc[2][8][4],
                                       int lane, int r0, int nb) {
    #pragma unroll
    for (int mt = 0; mt < 2; mt++)
        #pragma unroll
        for (int nt = 0; nt < 8; nt++)
            acc[mt][nt][0] = acc[mt][nt][1] = acc[mt][nt][2] = acc[mt][nt][3] = 0.f;

    const uint4* wb = Wf + ((nb >> 4) * 16) * 32 + lane;
    uint4 vc[4], vn[4];
    #pragma unroll
    for (int nt16 = 0; nt16 < 4; nt16++) vc[nt16] = wb[(nt16 * 16) * 32];

    #pragma unroll
    for (int ks = 0; ks < 16; ks++) {
        if (ks < 15) {
            #pragma unroll
            for (int nt16 = 0; nt16 < 4; nt16++) vn[nt16] = wb[(nt16 * 16 + ks + 1) * 32];
        }
        uint32_t a[2][4];
        #pragma unroll
        for (int mt = 0; mt < 2; mt++)
            ldm_x4(smem_u32(sA + (r0 + mt * 16 + (lane & 15)) * LDH
                            + ks * 16 + ((lane >> 4) << 3)),
                   a[mt][0], a[mt][1], a[mt][2], a[mt][3]);
        #pragma unroll
        for (int nt16 = 0; nt16 < 4; nt16++) {
            #pragma unroll
            for (int mt = 0; mt < 2; mt++) {
                mma_bf16(acc[mt][2 * nt16],     a[mt][0], a[mt][1], a[mt][2], a[mt][3],
                         vc[nt16].x, vc[nt16].y);
                mma_bf16(acc[mt][2 * nt16 + 1], a[mt][0], a[mt][1], a[mt][2], a[mt][3],
                         vc[nt16].z, vc[nt16].w);
            }
        }
        if (ks < 15) {
            #pragma unroll
            for (int nt16 = 0; nt16 < 4; nt16++) vc[nt16] = vn[nt16];
        }
    }
}

// Store a 32x64 warp-tile accumulator into a bf16 [64][LDH] buffer.
__device__ __forceinline__ void store_tile(__nv_bfloat16* dst, float acc[2][8][4],
                                           int r0, int nb, int grp, int tig) {
    #pragma unroll
    for (int mt = 0; mt < 2; mt++)
        #pragma unroll
        for (int nt = 0; nt < 8; nt++) {
            int col = nb + nt * 8 + tig * 2;
            int ra = r0 + mt * 16 + grp;
            *(__nv_bfloat162*)(dst + ra * LDH + col) =
                __floats2bfloat162_rn(acc[mt][nt][0], acc[mt][nt][1]);
            *(__nv_bfloat162*)(dst + (ra + 8) * LDH + col) =
                __floats2bfloat162_rn(acc[mt][nt][2], acc[mt][nt][3]);
        }
}

// SMEM: sX 33792 + sG 33792 + sY 33792 + sP 9216 + sC 256 + sBias 1024 = 111872
#define SMEM_BYTES 111872

__global__ void __launch_bounds__(256, 2)
attn_kernel(const float* __restrict__ x, float* __restrict__ out)
{
    extern __shared__ char smem_raw[];
    __nv_bfloat16* sX  = (__nv_bfloat16*)smem_raw;           // [64][LDH]
    __nv_bfloat16* sG  = sX + 64 * LDH;                      // [64][LDH]
    __nv_bfloat16* sY  = sG + 64 * LDH;                      // [64][LDH]  Y = X@W9
    __nv_bfloat16* sP  = sY + 64 * LDH;                      // [64][LDP]  P
    float*         sC  = (float*)(sP + 64 * LDP);            // [64]
    float*      sBias  = sC + 64;                            // [256]

    const int tid  = threadIdx.x;
    const int wid  = tid >> 5;
    const int lane = tid & 31;
    const int grp  = lane >> 2;
    const int tig  = lane & 3;

    const size_t base = (size_t)blockIdx.x * 64 * CH;
    const float* xrow = x   + base;
    float*       orow = out + base;

    // ---------------- Phase 0: bias + x tile (fp32 -> bf16) ----------------
    sBias[tid] = g_b9[tid];
    {
        const float4* xv = (const float4*)xrow;
        #pragma unroll
        for (int t = 0; t < 16; t++) {
            int i = tid + t * 256;
            int row = i >> 6;
            int colf = (i & 63) * 4;
            float4 v = xv[i];
            __nv_bfloat162* d = (__nv_bfloat162*)(sX + row * LDH + colf);
            d[0] = __floats2bfloat162_rn(v.x, v.y);
            d[1] = __floats2bfloat162_rn(v.z, v.w);
        }
    }
    __syncthreads();

    // c_j = x_j . w8 + s8 from sX (bf16; 4 threads per row)
    {
        int row = tid >> 2, q = tid & 3;
        const __nv_bfloat162* xr = (const __nv_bfloat162*)(sX + row * LDH + q * 64);
        float s = 0.f;
        #pragma unroll
        for (int j = 0; j < 32; j++) {
            float2 v = __bfloat1622float2(xr[j]);
            int c = q * 64 + j * 2;
            s += v.x * g_w8[c] + v.y * g_w8[c + 1];
        }
        s += __shfl_xor_sync(0xffffffffu, s, 1);
        s += __shfl_xor_sync(0xffffffffu, s, 2);
        if (q == 0) sC[row] = s + g_s8;
    }
    // sC consumed after the next barrier

    const int r0 = (wid >> 2) * 32;   // warp's 32 rows (weight gemms)
    const int nb = (wid & 3) * 64;    // warp's 64 cols

    float acc[2][8][4];

    // ------- Phase 1: dual GEMM, no intervening barrier -------
    gemm_f(g_M8f, sX, acc, lane, r0, nb);      // G = X @ M8 -> sG
    store_tile(sG, acc, r0, nb, grp, tig);
    gemm_f(g_W9f, sX, acc, lane, r0, nb);      // Y = X @ W9 -> sY
    store_tile(sY, acc, r0, nb, grp, tig);
    __syncthreads();

    // ------- Phase 2: fused S + softmax on warps 0-3 (in-register) -------
    if (wid < 4) {
        const int r0s = wid * 16;     // 16 rows, all 64 cols
        float sa[8][4];
        #pragma unroll
        for (int nt = 0; nt < 8; nt++)
            sa[nt][0] = sa[nt][1] = sa[nt][2] = sa[nt][3] = 0.f;
        #pragma unroll
        for (int ks = 0; ks < 16; ks++) {
            uint32_t a0, a1, a2, a3;
            ldm_x4(smem_u32(sG + (r0s + (lane & 15)) * LDH + ks * 16 + ((lane >> 4) << 3)),
                   a0, a1, a2, a3);
            #pragma unroll
            for (int nt16 = 0; nt16 < 4; nt16++) {
                uint32_t b0, b1, b2, b3;
                ldm_x4(smem_u32(sX + (nt16 * 16 + ((lane >> 4) << 3) + (lane & 7)) * LDH
                                + ks * 16 + (((lane >> 3) & 1) << 3)),
                       b0, b1, b2, b3);
                mma_bf16(sa[2 * nt16],     a0, a1, a2, a3, b0, b1);
                mma_bf16(sa[2 * nt16 + 1], a0, a1, a2, a3, b2, b3);
            }
        }
        const float SCALE = 1.0f / (256.0f * 16.0f * 0.70710678118654752f);
        float v0[16], v1[16];
        #pragma unroll
        for (int nt = 0; nt < 8; nt++) {
            int col = nt * 8 + tig * 2;
            float c0 = sC[col], c1 = sC[col + 1];
            v0[2 * nt] = (sa[nt][0] + c0) * SCALE; v0[2 * nt + 1] = (sa[nt][1] + c1) * SCALE;
            v1[2 * nt] = (sa[nt][2] + c0) * SCALE; v1[2 * nt + 1] = (sa[nt][3] + c1) * SCALE;
        }
        float m0 = v0[0], m1 = v1[0];
        #pragma unroll
        for (int i = 1; i < 16; i++) { m0 = fmaxf(m0, v0[i]); m1 = fmaxf(m1, v1[i]); }
        m0 = fmaxf(m0, __shfl_xor_sync(0xffffffffu, m0, 1));
        m0 = fmaxf(m0, __shfl_xor_sync(0xffffffffu, m0, 2));
        m1 = fmaxf(m1, __shfl_xor_sync(0xffffffffu, m1, 1));
        m1 = fmaxf(m1, __shfl_xor_sync(0xffffffffu, m1, 2));
        float s0 = 0.f, s1 = 0.f;
        #pragma unroll
        for (int i = 0; i < 16; i++) {
            v0[i] = __expf(v0[i] - m0); s0 += v0[i];
            v1[i] = __expf(v1[i] - m1); s1 += v1[i];
        }
        s0 += __shfl_xor_sync(0xffffffffu, s0, 1);
        s0 += __shfl_xor_sync(0xffffffffu, s0, 2);
        s1 += __shfl_xor_sync(0xffffffffu, s1, 1);
        s1 += __shfl_xor_sync(0xffffffffu, s1, 2);
        float i0 = 1.0f / s0, i1 = 1.0f / s1;
        int ra = r0s + grp, rb = ra + 8;
        #pragma unroll
        for (int nt = 0; nt < 8; nt++) {
            *(__nv_bfloat162*)(sP + ra * LDP + nt * 8 + tig * 2) =
                __floats2bfloat162_rn(v0[2 * nt] * i0, v0[2 * nt + 1] * i0);
            *(__nv_bfloat162*)(sP + rb * LDP + nt * 8 + tig * 2) =
                __floats2bfloat162_rn(v1[2 * nt] * i1, v1[2 * nt + 1] * i1);
        }
    } else {
        // warps 4-7: pull the epilogue residual x into L2 (64KB = 512 lines)
        int t = tid - 128;
        #pragma unroll
        for (int i = 0; i < 4; i++)
            asm volatile("prefetch.global.L2 [%0];"
                         :: "l"(xrow + (t + i * 128) * 32));
    }
    __syncthreads();

    // ------- Phase 3: out = P @ Y + b9 + x (K=64, smem operands) -------
    {
        #pragma unroll
        for (int mt = 0; mt < 2; mt++)
            #pragma unroll
            for (int nt = 0; nt < 8; nt++)
                acc[mt][nt][0] = acc[mt][nt][1] = acc[mt][nt][2] = acc[mt][nt][3] = 0.f;
        #pragma unroll
        for (int ks = 0; ks < 4; ks++) {
            uint32_t a[2][4];
            #pragma unroll
            for (int mt = 0; mt < 2; mt++)
                ldm_x4(smem_u32(sP + (r0 + mt * 16 + (lane & 15)) * LDP
                                + ks * 16 + ((lane >> 4) << 3)),
                       a[mt][0], a[mt][1], a[mt][2], a[mt][3]);
            #pragma unroll
            for (int nt16 = 0; nt16 < 4; nt16++) {
                uint32_t b0, b1, b2, b3;
                ldm_x4t(smem_u32(sY + (ks * 16 + (lane & 15)) * LDH
                                 + nb + nt16 * 16 + ((lane >> 4) << 3)),
                        b0, b1, b2, b3);
                #pragma unroll
                for (int mt = 0; mt < 2; mt++) {
                    mma_bf16(acc[mt][2 * nt16],     a[mt][0], a[mt][1], a[mt][2], a[mt][3], b0, b1);
                    mma_bf16(acc[mt][2 * nt16 + 1], a[mt][0], a[mt][1], a[mt][2], a[mt][3], b2, b3);
                }
            }
        }
        #pragma unroll
        for (int mt = 0; mt < 2; mt++)
            #pragma unroll
            for (int nt = 0; nt < 8; nt++) {
                int col = nb + nt * 8 + tig * 2;
                float b0v = sBias[col], b1v = sBias[col + 1];
                int ra = r0 + mt * 16 + grp, rb = ra + 8;
                float2 xa = *(const float2*)(xrow + ra * CH + col);
                float2 xb = *(const float2*)(xrow + rb * CH + col);
                *(float2*)(orow + ra * CH + col) =
                    make_float2(acc[mt][nt][0] + b0v + xa.x, acc[mt][nt][1] + b1v + xa.y);
                *(float2*)(orow + rb * CH + col) =
                    make_float2(acc[mt][nt][2] + b0v + xb.x, acc[mt][nt][3] + b1v + xb.y);
            }
    }
}

extern "C" void kernel_launch(void* const* d_in, const int* in_sizes, int n_in,
                              void* d_out, int out_size) {
    const float* x  = (const float*)d_in[0];
    const float* Wq = (const float*)d_in[1];
    const float* bq = (const float*)d_in[2];
    const float* Wk = (const float*)d_in[3];
    const float* bk = (const float*)d_in[4];
    const float* Wv = (const float*)d_in[5];
    const float* bv = (const float*)d_in[6];
    const float* Wo = (const float*)d_in[7];
    const float* bo = (const float*)d_in[8];
    float* out = (float*)d_out;

    cudaFuncSetAttribute(setup_kernel, cudaFuncAttributeMaxDynamicSharedMemorySize,
                         SETUP_SMEM_BYTES);
    setup_kernel<<<dim3(8, 8, 3), 256, SETUP_SMEM_BYTES>>>(Wq, Wk, Wv, Wo, bq, bk, bv, bo);

    cudaFuncSetAttribute(attn_kernel, cudaFuncAttributeMaxDynamicSharedMemorySize, SMEM_BYTES);
    attn_kernel<<<2048, 256, SMEM_BYTES>>>(x, out);
}